// round 1
// baseline (speedup 1.0000x reference)
#include <cuda_runtime.h>

#define NEG_BIG 1e30f

// Scratch (B*Lc = 4096 rows)
__device__ float g_m[4096];
__device__ float g_c1[4096];
__device__ float g_U[4096];

__device__ __forceinline__ float wred_max(float v) {
#pragma unroll
    for (int o = 16; o; o >>= 1) v = fmaxf(v, __shfl_xor_sync(0xffffffffu, v, o));
    return v;
}
__device__ __forceinline__ float wred_sum(float v) {
#pragma unroll
    for (int o = 16; o; o >>= 1) v += __shfl_xor_sync(0xffffffffu, v, o);
    return v;
}

// Kernel 1: per-row attention. Grid (16 chunks, 8 batches), 256 threads.
// Warp w handles rows i0..i0+3; lane l is j-parallel (j = l and l+32).
__global__ __launch_bounds__(256) void attn_rows_kernel(
    const float* __restrict__ context,   // (8, 512, 256)
    const float* __restrict__ question,  // (8, 64, 256)
    const int*   __restrict__ mask,      // (8, 64)
    const float* __restrict__ att_w,     // (768,)
    const float* __restrict__ att_b,     // (1,)
    const float* __restrict__ w_in,      // (256,)
    const float* __restrict__ w_mem)     // (256,)
{
    const int b     = blockIdx.y;
    const int chunk = blockIdx.x;
    const int tid   = threadIdx.x;
    const int w     = tid >> 5;
    const int l     = tid & 31;

    __shared__ float cwsh[8][4][256];   // per-warp cw rows (32 KB)
    __shared__ float sqc[64];           // sq[j] + att_b - NEG_BIG*(1-mask[j])
    __shared__ float q1sh[64];          // question[j] . w_mem

    const float* qbase = question + (size_t)(b * 64) * 256;

    // ---- per-j scalars: sq, q1 (threads 0..63) ----
    if (tid < 64) {
        const float4* qrow = (const float4*)(qbase + tid * 256);
        const float4* wq4  = (const float4*)(att_w + 256);
        const float4* wm4  = (const float4*)(w_mem);
        float sq = 0.f, q1 = 0.f;
#pragma unroll 8
        for (int d = 0; d < 64; d++) {
            float4 v = __ldg(&qrow[d]);
            float4 a = __ldg(&wq4[d]);
            float4 c = __ldg(&wm4[d]);
            sq += v.x * a.x + v.y * a.y + v.z * a.z + v.w * a.w;
            q1 += v.x * c.x + v.y * c.y + v.z * c.z + v.w * c.w;
        }
        float mk = (float)__ldg(&mask[b * 64 + tid]);
        sqc[tid]  = sq + __ldg(&att_b[0]) - NEG_BIG * (1.0f - mk);
        q1sh[tid] = q1;
    }

    // ---- stage cw rows + row scalars sc, ctx1 ----
    const int d0 = l * 8;
    const int i0 = chunk * 32 + w * 4;

    float4 wpa = __ldg((const float4*)(att_w + 512 + d0));
    float4 wpb = __ldg((const float4*)(att_w + 512 + d0 + 4));
    float4 wca = __ldg((const float4*)(att_w + d0));
    float4 wcb = __ldg((const float4*)(att_w + d0 + 4));
    float4 wia = __ldg((const float4*)(w_in + d0));
    float4 wib = __ldg((const float4*)(w_in + d0 + 4));

    float sc[4], c1[4];
#pragma unroll
    for (int r = 0; r < 4; r++) {
        const float* crow = context + (size_t)(b * 512 + i0 + r) * 256 + d0;
        float4 ca = __ldg((const float4*)crow);
        float4 cb = __ldg((const float4*)(crow + 4));
        float4 cwa = make_float4(ca.x * wpa.x, ca.y * wpa.y, ca.z * wpa.z, ca.w * wpa.w);
        float4 cwb = make_float4(cb.x * wpb.x, cb.y * wpb.y, cb.z * wpb.z, cb.w * wpb.w);
        *(float4*)&cwsh[w][r][d0]     = cwa;
        *(float4*)&cwsh[w][r][d0 + 4] = cwb;
        float scp = ca.x * wca.x + ca.y * wca.y + ca.z * wca.z + ca.w * wca.w
                  + cb.x * wcb.x + cb.y * wcb.y + cb.z * wcb.z + cb.w * wcb.w;
        float c1p = ca.x * wia.x + ca.y * wia.y + ca.z * wia.z + ca.w * wia.w
                  + cb.x * wib.x + cb.y * wib.y + cb.z * wib.z + cb.w * wib.w;
        sc[r] = wred_sum(scp);
        c1[r] = wred_sum(c1p);
    }

    __syncthreads();  // sqc/q1sh + cwsh visible

    // ---- main loop: sp dots, 4 rows x 2 j per lane ----
    const float* q0p = qbase + (size_t)l * 256;
    const float* q1p = qbase + (size_t)(l + 32) * 256;

    float acc[4][2];
#pragma unroll
    for (int r = 0; r < 4; r++) { acc[r][0] = 0.f; acc[r][1] = 0.f; }

#pragma unroll 4
    for (int d = 0; d < 256; d += 4) {
        float4 qa = __ldg((const float4*)(q0p + d));
        float4 qb = __ldg((const float4*)(q1p + d));
#pragma unroll
        for (int r = 0; r < 4; r++) {
            float4 cw = *(const float4*)&cwsh[w][r][d];
            acc[r][0] += cw.x * qa.x + cw.y * qa.y + cw.z * qa.z + cw.w * qa.w;
            acc[r][1] += cw.x * qb.x + cw.y * qb.y + cw.z * qb.z + cw.w * qb.w;
        }
    }

    // ---- epilogue: softmax over j, U; write scratch ----
    const float sq0 = sqc[l];
    const float sq1 = sqc[l + 32];
    const float qv0 = q1sh[l];
    const float qv1 = q1sh[l + 32];

#pragma unroll
    for (int r = 0; r < 4; r++) {
        float a0 = acc[r][0] + sc[r] + sq0;
        float a1 = acc[r][1] + sc[r] + sq1;
        float m  = wred_max(fmaxf(a0, a1));
        float e0 = __expf(a0 - m);
        float e1 = __expf(a1 - m);
        float den = wred_sum(e0 + e1);
        float num = wred_sum(e0 * qv0 + e1 * qv1);
        if (l == 0) {
            int idx = b * 512 + i0 + r;
            g_m[idx]  = m;
            g_c1[idx] = c1[r];
            g_U[idx]  = num / den;
        }
    }
}

// Kernel 2: softmax over i of row-maxes -> H per batch; emit G.
__global__ __launch_bounds__(512) void finalize_kernel(float* __restrict__ out)
{
    const int b = blockIdx.x;
    const int i = threadIdx.x;
    const int idx = b * 512 + i;
    const int w = i >> 5, l = i & 31;

    float m  = g_m[idx];
    float c1 = g_c1[idx];
    float U  = g_U[idx];

    __shared__ float redA[16];
    __shared__ float redB[16];

    // block max of m
    float M = wred_max(m);
    if (l == 0) redA[w] = M;
    __syncthreads();
    if (w == 0) {
        float v = (l < 16) ? redA[l] : -3.4e38f;
#pragma unroll
        for (int o = 8; o; o >>= 1) v = fmaxf(v, __shfl_xor_sync(0xffffffffu, v, o));
        if (l == 0) redA[0] = v;
    }
    __syncthreads();
    M = redA[0];
    __syncthreads();

    // sums: e, e*c1
    float e = __expf(m - M);
    float se  = wred_sum(e);
    float sec = wred_sum(e * c1);
    if (l == 0) { redA[w] = se; redB[w] = sec; }
    __syncthreads();
    if (w == 0) {
        float a = (l < 16) ? redA[l] : 0.f;
        float c = (l < 16) ? redB[l] : 0.f;
#pragma unroll
        for (int o = 8; o; o >>= 1) {
            a += __shfl_xor_sync(0xffffffffu, a, o);
            c += __shfl_xor_sync(0xffffffffu, c, o);
        }
        if (l == 0) { redA[0] = a; redB[0] = c; }
    }
    __syncthreads();
    float H = redB[0] / redA[0];

    float4 o = make_float4(c1, U, c1 * U, U * H);
    ((float4*)out)[idx] = o;
}

extern "C" void kernel_launch(void* const* d_in, const int* in_sizes, int n_in,
                              void* d_out, int out_size)
{
    const float* context  = (const float*)d_in[0];
    const float* question = (const float*)d_in[1];
    const int*   mask     = (const int*)d_in[2];
    const float* att_w    = (const float*)d_in[3];
    const float* att_b    = (const float*)d_in[4];
    const float* w_in     = (const float*)d_in[5];
    const float* w_mem    = (const float*)d_in[6];

    dim3 grid(16, 8);
    attn_rows_kernel<<<grid, 256>>>(context, question, mask, att_w, att_b, w_in, w_mem);
    finalize_kernel<<<8, 512>>>((float*)d_out);
}

// round 2
// speedup vs baseline: 2.6419x; 2.6419x over previous
#include <cuda_runtime.h>

#define NEG_BIG 1e30f

// row pitch: 260 floats = 1040 B. 1040 mod 128 = 16 -> successive rows land on
// distinct 16B bank slots => conflict-free LDS.128 for both 8-row and 4-row
// access patterns, no padding-vs-XOR swizzle needed.
#define PITCHF 260
#define PITCH16 65      // pitch in 16-byte units

// Scratch (B*Lc = 4096 rows)
__device__ float g_m[4096];
__device__ float g_c1[4096];
__device__ float g_U[4096];

// packed fp32x2 FMA (Blackwell): d = a*b + d on both 32-bit halves
__device__ __forceinline__ void ffma2(unsigned long long& d,
                                      unsigned long long a,
                                      unsigned long long b) {
    asm("fma.rn.f32x2 %0, %1, %2, %0;" : "+l"(d) : "l"(a), "l"(b));
}

union U64f2 { unsigned long long u; float2 f; };

__device__ __forceinline__ float wred_max(float v) {
#pragma unroll
    for (int o = 16; o; o >>= 1) v = fmaxf(v, __shfl_xor_sync(0xffffffffu, v, o));
    return v;
}
__device__ __forceinline__ float wred_sum(float v) {
#pragma unroll
    for (int o = 16; o; o >>= 1) v += __shfl_xor_sync(0xffffffffu, v, o);
    return v;
}

// smem layout (floats)
#define OFF_Q    0                     // 64 * 260
#define OFF_CW   (64 * PITCHF)         // 32 * 260
#define OFF_SQC  (OFF_CW + 32 * PITCHF)  // 64
#define OFF_Q1   (OFF_SQC + 64)          // 64
#define OFF_SC   (OFF_Q1 + 64)           // 32
#define OFF_C1   (OFF_SC + 32)           // 32
#define OFF_RM   (OFF_C1 + 32)           // 32*4
#define OFF_RS   (OFF_RM + 128)          // 32*4
#define OFF_RN   (OFF_RS + 128)          // 32*4
#define SMEM_FLOATS (OFF_RN + 128)
#define SMEM_BYTES  (SMEM_FLOATS * 4)    // 102144

// Kernel 1: grid (16 i-chunks, 8 batches), 256 threads.
// Block tile 32i x 64j x 256d. Warps: wi(2) x wj(4), warp tile 16i x 16j.
// Lane: li = l>>2 (0..7), lj = l&3. Lane tile: rows {li, li+8}, cols {lj,lj+4,lj+8,lj+12}.
__global__ __launch_bounds__(256) void attn_main(
    const float* __restrict__ context,   // (8, 512, 256)
    const float* __restrict__ question,  // (8, 64, 256)
    const int*   __restrict__ mask,      // (8, 64)
    const float* __restrict__ att_w,     // (768,)
    const float* __restrict__ att_b,     // (1,)
    const float* __restrict__ w_in,      // (256,)
    const float* __restrict__ w_mem)     // (256,)
{
    extern __shared__ float sm[];
    float* qs   = sm + OFF_Q;
    float* cws  = sm + OFF_CW;
    float* sqc  = sm + OFF_SQC;
    float* q1sh = sm + OFF_Q1;
    float* scsh = sm + OFF_SC;
    float* c1sh = sm + OFF_C1;
    float* redM = sm + OFF_RM;
    float* redS = sm + OFF_RS;
    float* redN = sm + OFF_RN;

    const int b      = blockIdx.y;
    const int blockI = blockIdx.x * 32;
    const int tid    = threadIdx.x;

    const float* qbase = question + (size_t)(b * 64) * 256;
    const float* cbase = context  + (size_t)(b * 512 + blockI) * 256;

    // ---- stage Q tile (64 x 256) + per-j scalars sq, q1 ----
    {
        const int jq = tid >> 2;        // 0..63
        const int l4 = tid & 3;         // 4 threads per row
        const float4* qrow = (const float4*)(qbase + (size_t)jq * 256);
        float4* qsrow = (float4*)(qs + jq * PITCHF);
        const float4* wq4 = (const float4*)(att_w + 256);
        const float4* wm4 = (const float4*)(w_mem);
        float sq = 0.f, q1 = 0.f;
#pragma unroll
        for (int k = 0; k < 16; k++) {
            int c4 = l4 + (k << 2);
            float4 v = __ldg(&qrow[c4]);
            qsrow[c4] = v;
            float4 a = __ldg(&wq4[c4]);
            float4 m = __ldg(&wm4[c4]);
            sq += v.x * a.x + v.y * a.y + v.z * a.z + v.w * a.w;
            q1 += v.x * m.x + v.y * m.y + v.z * m.z + v.w * m.w;
        }
        sq += __shfl_xor_sync(0xffffffffu, sq, 1);
        sq += __shfl_xor_sync(0xffffffffu, sq, 2);
        q1 += __shfl_xor_sync(0xffffffffu, q1, 1);
        q1 += __shfl_xor_sync(0xffffffffu, q1, 2);
        if (l4 == 0) {
            float mk = (float)__ldg(&mask[b * 64 + jq]);
            sqc[jq]  = sq + __ldg(&att_b[0]) - NEG_BIG * (1.0f - mk);
            q1sh[jq] = q1;
        }
    }

    // ---- stage CW tile (32 x 256) + per-i scalars sc, c1 ----
    {
        const int ic = tid >> 3;        // 0..31
        const int l8 = tid & 7;         // 8 threads per row
        const float4* crow = (const float4*)(cbase + (size_t)ic * 256);
        float4* cwrow = (float4*)(cws + ic * PITCHF);
        const float4* wp4 = (const float4*)(att_w + 512);
        const float4* wc4 = (const float4*)(att_w);
        const float4* wi4 = (const float4*)(w_in);
        float sc = 0.f, c1 = 0.f;
#pragma unroll
        for (int k = 0; k < 8; k++) {
            int c4 = l8 + (k << 3);
            float4 v = __ldg(&crow[c4]);
            float4 p = __ldg(&wp4[c4]);
            cwrow[c4] = make_float4(v.x * p.x, v.y * p.y, v.z * p.z, v.w * p.w);
            float4 a = __ldg(&wc4[c4]);
            float4 m = __ldg(&wi4[c4]);
            sc += v.x * a.x + v.y * a.y + v.z * a.z + v.w * a.w;
            c1 += v.x * m.x + v.y * m.y + v.z * m.z + v.w * m.w;
        }
        sc += __shfl_xor_sync(0xffffffffu, sc, 1);
        sc += __shfl_xor_sync(0xffffffffu, sc, 2);
        sc += __shfl_xor_sync(0xffffffffu, sc, 4);
        c1 += __shfl_xor_sync(0xffffffffu, c1, 1);
        c1 += __shfl_xor_sync(0xffffffffu, c1, 2);
        c1 += __shfl_xor_sync(0xffffffffu, c1, 4);
        if (l8 == 0) { scsh[ic] = sc; c1sh[ic] = c1; }
    }

    __syncthreads();

    // ---- mainloop: S = CW * Q^T, packed f32x2 along d ----
    const int w  = tid >> 5;
    const int l  = tid & 31;
    const int wi = w >> 2;     // 0..1
    const int wj = w & 3;      // 0..3
    const int li = l >> 2;     // 0..7
    const int lj = l & 3;      // 0..3

    const ulonglong2* cr0 = (const ulonglong2*)cws + (wi * 16 + li)     * PITCH16;
    const ulonglong2* cr1 = (const ulonglong2*)cws + (wi * 16 + li + 8) * PITCH16;
    const ulonglong2* q0  = (const ulonglong2*)qs  + (wj * 16 + lj)      * PITCH16;
    const ulonglong2* q1r = (const ulonglong2*)qs  + (wj * 16 + lj + 4)  * PITCH16;
    const ulonglong2* q2r = (const ulonglong2*)qs  + (wj * 16 + lj + 8)  * PITCH16;
    const ulonglong2* q3r = (const ulonglong2*)qs  + (wj * 16 + lj + 12) * PITCH16;

    unsigned long long acc[2][4];
#pragma unroll
    for (int r = 0; r < 2; r++)
#pragma unroll
        for (int j = 0; j < 4; j++) acc[r][j] = 0ull;

#pragma unroll 4
    for (int d = 0; d < 64; d++) {
        ulonglong2 a0 = cr0[d];
        ulonglong2 a1 = cr1[d];
        ulonglong2 b0 = q0[d];
        ulonglong2 b1 = q1r[d];
        ulonglong2 b2 = q2r[d];
        ulonglong2 b3 = q3r[d];
        ffma2(acc[0][0], a0.x, b0.x); ffma2(acc[0][0], a0.y, b0.y);
        ffma2(acc[0][1], a0.x, b1.x); ffma2(acc[0][1], a0.y, b1.y);
        ffma2(acc[0][2], a0.x, b2.x); ffma2(acc[0][2], a0.y, b2.y);
        ffma2(acc[0][3], a0.x, b3.x); ffma2(acc[0][3], a0.y, b3.y);
        ffma2(acc[1][0], a1.x, b0.x); ffma2(acc[1][0], a1.y, b0.y);
        ffma2(acc[1][1], a1.x, b1.x); ffma2(acc[1][1], a1.y, b1.y);
        ffma2(acc[1][2], a1.x, b2.x); ffma2(acc[1][2], a1.y, b2.y);
        ffma2(acc[1][3], a1.x, b3.x); ffma2(acc[1][3], a1.y, b3.y);
    }

    // ---- epilogue: softmax over j (64), U per row; write scratch ----
    const int il0 = wi * 16 + li;       // local row of acc[0]
    const int il1 = il0 + 8;            // local row of acc[1]
    const float sc0 = scsh[il0];
    const float sc1 = scsh[il1];

    float s0[4], s1[4], qv[4];
#pragma unroll
    for (int jj = 0; jj < 4; jj++) {
        int j = wj * 16 + lj + 4 * jj;
        float sq = sqc[j];
        qv[jj] = q1sh[j];
        U64f2 u0; u0.u = acc[0][jj];
        U64f2 u1; u1.u = acc[1][jj];
        s0[jj] = u0.f.x + u0.f.y + sc0 + sq;
        s1[jj] = u1.f.x + u1.f.y + sc1 + sq;
    }

    float m0 = fmaxf(fmaxf(s0[0], s0[1]), fmaxf(s0[2], s0[3]));
    float m1 = fmaxf(fmaxf(s1[0], s1[1]), fmaxf(s1[2], s1[3]));
    m0 = fmaxf(m0, __shfl_xor_sync(0xffffffffu, m0, 1));
    m0 = fmaxf(m0, __shfl_xor_sync(0xffffffffu, m0, 2));
    m1 = fmaxf(m1, __shfl_xor_sync(0xffffffffu, m1, 1));
    m1 = fmaxf(m1, __shfl_xor_sync(0xffffffffu, m1, 2));
    if (lj == 0) {
        redM[il0 * 4 + wj] = m0;
        redM[il1 * 4 + wj] = m1;
    }
    __syncthreads();

    float4 M4a = *(const float4*)&redM[il0 * 4];
    float4 M4b = *(const float4*)&redM[il1 * 4];
    const float M0 = fmaxf(fmaxf(M4a.x, M4a.y), fmaxf(M4a.z, M4a.w));
    const float M1 = fmaxf(fmaxf(M4b.x, M4b.y), fmaxf(M4b.z, M4b.w));

    float se0 = 0.f, se1 = 0.f, sn0 = 0.f, sn1 = 0.f;
#pragma unroll
    for (int jj = 0; jj < 4; jj++) {
        float e0 = __expf(s0[jj] - M0);
        float e1 = __expf(s1[jj] - M1);
        se0 += e0; sn0 += e0 * qv[jj];
        se1 += e1; sn1 += e1 * qv[jj];
    }
    se0 += __shfl_xor_sync(0xffffffffu, se0, 1);
    se0 += __shfl_xor_sync(0xffffffffu, se0, 2);
    sn0 += __shfl_xor_sync(0xffffffffu, sn0, 1);
    sn0 += __shfl_xor_sync(0xffffffffu, sn0, 2);
    se1 += __shfl_xor_sync(0xffffffffu, se1, 1);
    se1 += __shfl_xor_sync(0xffffffffu, se1, 2);
    sn1 += __shfl_xor_sync(0xffffffffu, sn1, 1);
    sn1 += __shfl_xor_sync(0xffffffffu, sn1, 2);
    if (lj == 0) {
        redS[il0 * 4 + wj] = se0;
        redS[il1 * 4 + wj] = se1;
        redN[il0 * 4 + wj] = sn0;
        redN[il1 * 4 + wj] = sn1;
    }
    __syncthreads();

    if (wj == 0 && lj == 0) {
        float4 S0 = *(const float4*)&redS[il0 * 4];
        float4 S1 = *(const float4*)&redS[il1 * 4];
        float4 N0 = *(const float4*)&redN[il0 * 4];
        float4 N1 = *(const float4*)&redN[il1 * 4];
        int idx0 = b * 512 + blockI + il0;
        int idx1 = b * 512 + blockI + il1;
        g_m[idx0]  = M0;
        g_m[idx1]  = M1;
        g_c1[idx0] = c1sh[il0];
        g_c1[idx1] = c1sh[il1];
        g_U[idx0] = (N0.x + N0.y + N0.z + N0.w) / (S0.x + S0.y + S0.z + S0.w);
        g_U[idx1] = (N1.x + N1.y + N1.z + N1.w) / (S1.x + S1.y + S1.z + S1.w);
    }
}

// Kernel 2: softmax over i of row-maxes -> H per batch; emit G.
__global__ __launch_bounds__(512) void finalize_kernel(float* __restrict__ out)
{
    const int b = blockIdx.x;
    const int i = threadIdx.x;
    const int idx = b * 512 + i;
    const int w = i >> 5, l = i & 31;

    float m  = g_m[idx];
    float c1 = g_c1[idx];
    float U  = g_U[idx];

    __shared__ float redA[16];
    __shared__ float redB[16];

    float M = wred_max(m);
    if (l == 0) redA[w] = M;
    __syncthreads();
    if (w == 0) {
        float v = (l < 16) ? redA[l] : -3.4e38f;
#pragma unroll
        for (int o = 8; o; o >>= 1) v = fmaxf(v, __shfl_xor_sync(0xffffffffu, v, o));
        if (l == 0) redA[0] = v;
    }
    __syncthreads();
    M = redA[0];
    __syncthreads();

    float e = __expf(m - M);
    float se  = wred_sum(e);
    float sec = wred_sum(e * c1);
    if (l == 0) { redA[w] = se; redB[w] = sec; }
    __syncthreads();
    if (w == 0) {
        float a = (l < 16) ? redA[l] : 0.f;
        float c = (l < 16) ? redB[l] : 0.f;
#pragma unroll
        for (int o = 8; o; o >>= 1) {
            a += __shfl_xor_sync(0xffffffffu, a, o);
            c += __shfl_xor_sync(0xffffffffu, c, o);
        }
        if (l == 0) { redA[0] = a; redB[0] = c; }
    }
    __syncthreads();
    float H = redB[0] / redA[0];

    float4 o = make_float4(c1, U, c1 * U, U * H);
    ((float4*)out)[idx] = o;
}

extern "C" void kernel_launch(void* const* d_in, const int* in_sizes, int n_in,
                              void* d_out, int out_size)
{
    const float* context  = (const float*)d_in[0];
    const float* question = (const float*)d_in[1];
    const int*   mask     = (const int*)d_in[2];
    const float* att_w    = (const float*)d_in[3];
    const float* att_b    = (const float*)d_in[4];
    const float* w_in     = (const float*)d_in[5];
    const float* w_mem    = (const float*)d_in[6];

    cudaFuncSetAttribute(attn_main,
                         cudaFuncAttributeMaxDynamicSharedMemorySize, SMEM_BYTES);

    dim3 grid(16, 8);
    attn_main<<<grid, 256, SMEM_BYTES>>>(context, question, mask,
                                         att_w, att_b, w_in, w_mem);
    finalize_kernel<<<8, 512>>>((float*)d_out);
}